// round 1
// baseline (speedup 1.0000x reference)
#include <cuda_runtime.h>
#include <math.h>

#define B_  64
#define S_  256
#define H_  768
#define T_  13
#define D_  64
#define NEGC 1000000000000.0f

#define M1 (B_*S_)      // 16384
#define N1 (T_*2*D_)    // 1664
#define K1 H_           // 768

// Scratch (allocation-free rule: __device__ globals)
__device__ float g_q[(size_t)B_*T_*S_*D_];   // [b, h, s, d]
__device__ float g_k[(size_t)B_*T_*S_*D_];   // [b, h, s, d]
__device__ float g_cos[S_*(D_/2)];
__device__ float g_sin[S_*(D_/2)];

// ---------------------------------------------------------------------------
// RoPE table in fp64 (8192 values, trivial cost; removes fast-math sinf risk)
// ---------------------------------------------------------------------------
__global__ void rope_table_kernel() {
    int idx = blockIdx.x * blockDim.x + threadIdx.x;   // 0..8191
    if (idx >= S_ * (D_/2)) return;
    int s = idx >> 5;       // position
    int i = idx & 31;       // freq index
    double inv = pow(10000.0, -2.0 * (double)i / (double)D_);
    double ang = (double)s * inv;
    g_cos[idx] = (float)cos(ang);
    g_sin[idx] = (float)sin(ang);
}

// ---------------------------------------------------------------------------
// GEMM1: C[16384,1664] = X @ W + b, fused RoPE, scatter to g_q / g_k
// 128x128 block tile, BK=16, 8x8 per-thread micro-tile, 256 threads
// blockIdx.x = head (BN=128 == 2*D exactly), blockIdx.y = row tile
// ---------------------------------------------------------------------------
__global__ __launch_bounds__(256) void gemm1_rope_kernel(
    const float* __restrict__ X, const float* __restrict__ W,
    const float* __restrict__ bias)
{
    __shared__ float As[16][132];   // [k][m], padded
    __shared__ float Bs[16][132];   // [k][n], padded

    const int tid = threadIdx.x;
    const int bx  = blockIdx.x;     // head tile: 0..12
    const int by  = blockIdx.y;     // row tile:  0..127
    const int tx  = tid & 15;
    const int ty  = tid >> 4;

    float acc[8][8];
    #pragma unroll
    for (int i = 0; i < 8; i++)
        #pragma unroll
        for (int j = 0; j < 8; j++) acc[i][j] = 0.0f;

    const int colBase = bx * 128;

    for (int k0 = 0; k0 < K1; k0 += 16) {
        // Load A tile (128 rows x 16 k), store transposed As[k][m]
        #pragma unroll
        for (int t = 0; t < 2; t++) {
            int f  = tid + t * 256;         // 512 float4s
            int ar = f >> 2;                // row 0..127
            int ac = (f & 3) << 2;          // k offset 0,4,8,12
            float4 v = *reinterpret_cast<const float4*>(
                &X[(size_t)(by * 128 + ar) * K1 + k0 + ac]);
            As[ac + 0][ar] = v.x;
            As[ac + 1][ar] = v.y;
            As[ac + 2][ar] = v.z;
            As[ac + 3][ar] = v.w;
        }
        // Load B tile (16 k x 128 cols), row-major Bs[k][n]
        #pragma unroll
        for (int t = 0; t < 2; t++) {
            int f  = tid + t * 256;
            int br = f >> 5;                // k 0..15
            int bc = (f & 31) << 2;         // col 0..124
            *reinterpret_cast<float4*>(&Bs[br][bc]) =
                *reinterpret_cast<const float4*>(
                    &W[(size_t)(k0 + br) * N1 + colBase + bc]);
        }
        __syncthreads();

        #pragma unroll
        for (int k = 0; k < 16; k++) {
            float a[8], b[8];
            float4 a0 = *reinterpret_cast<const float4*>(&As[k][ty * 8]);
            float4 a1 = *reinterpret_cast<const float4*>(&As[k][ty * 8 + 4]);
            float4 b0 = *reinterpret_cast<const float4*>(&Bs[k][tx * 8]);
            float4 b1 = *reinterpret_cast<const float4*>(&Bs[k][tx * 8 + 4]);
            a[0]=a0.x; a[1]=a0.y; a[2]=a0.z; a[3]=a0.w;
            a[4]=a1.x; a[5]=a1.y; a[6]=a1.z; a[7]=a1.w;
            b[0]=b0.x; b[1]=b0.y; b[2]=b0.z; b[3]=b0.w;
            b[4]=b1.x; b[5]=b1.y; b[6]=b1.z; b[7]=b1.w;
            #pragma unroll
            for (int i = 0; i < 8; i++)
                #pragma unroll
                for (int j = 0; j < 8; j++)
                    acc[i][j] += a[i] * b[j];
        }
        __syncthreads();
    }

    // Epilogue: bias + RoPE (pairs are within each thread's 8 cols) + scatter
    const int h = bx;
    #pragma unroll
    for (int i = 0; i < 8; i++) {
        int r = by * 128 + ty * 8 + i;
        int b = r >> 8;          // batch
        int s = r & 255;         // position
        #pragma unroll
        for (int j = 0; j < 8; j += 2) {
            int c128 = tx * 8 + j;           // 0..127 within head
            int d    = c128 & 63;            // dim within q or k
            bool isq = (c128 < 64);
            float x = acc[i][j]     + bias[h * 128 + c128];
            float y = acc[i][j + 1] + bias[h * 128 + c128 + 1];
            int   pi = d >> 1;
            float cs = g_cos[s * 32 + pi];
            float sn = g_sin[s * 32 + pi];
            float xo = x * cs - y * sn;      // even: x*cos - y*sin
            float yo = y * cs + x * sn;      // odd:  y*cos + x*sin
            float* dst = isq ? g_q : g_k;
            size_t off = (((size_t)(b * T_ + h)) * S_ + s) * D_ + d;
            dst[off]     = xo;
            dst[off + 1] = yo;
        }
    }
}

// ---------------------------------------------------------------------------
// GEMM2: per (b,h): logits[m,n] = sum_d q[m,d]*k[n,d], + masks + scale
// 128x128 block tile of the 256x256 output, K split in 2 chunks of 32.
// grid = (2, 2, 832), 256 threads, 8x8 micro-tile.
// ---------------------------------------------------------------------------
__global__ __launch_bounds__(256) void gemm2_mask_kernel(
    const float* __restrict__ attn_mask, float* __restrict__ out)
{
    __shared__ float Qs[32][132];   // [d][m]
    __shared__ float Ks[32][132];   // [d][n]
    __shared__ float pads[128];

    const int tid = threadIdx.x;
    const int z   = blockIdx.z;          // b*13 + h
    const int b   = z / T_;
    const int n0  = blockIdx.x * 128;
    const int m0  = blockIdx.y * 128;
    const int tx  = tid & 15;
    const int ty  = tid >> 4;

    if (tid < 128) pads[tid] = attn_mask[b * S_ + n0 + tid];

    const float* qbase = g_q + (size_t)z * S_ * D_;
    const float* kbase = g_k + (size_t)z * S_ * D_;

    float acc[8][8];
    #pragma unroll
    for (int i = 0; i < 8; i++)
        #pragma unroll
        for (int j = 0; j < 8; j++) acc[i][j] = 0.0f;

    for (int k0 = 0; k0 < D_; k0 += 32) {
        // Load 128 rows x 32 d of Q and K, transposed into [d][row]
        #pragma unroll
        for (int t = 0; t < 4; t++) {
            int f  = tid + t * 256;          // 1024 float4s
            int m  = f >> 3;                 // row 0..127
            int c4 = (f & 7) << 2;           // d offset 0..28
            float4 vq = *reinterpret_cast<const float4*>(
                &qbase[(size_t)(m0 + m) * D_ + k0 + c4]);
            Qs[c4 + 0][m] = vq.x; Qs[c4 + 1][m] = vq.y;
            Qs[c4 + 2][m] = vq.z; Qs[c4 + 3][m] = vq.w;
            float4 vk = *reinterpret_cast<const float4*>(
                &kbase[(size_t)(n0 + m) * D_ + k0 + c4]);
            Ks[c4 + 0][m] = vk.x; Ks[c4 + 1][m] = vk.y;
            Ks[c4 + 2][m] = vk.z; Ks[c4 + 3][m] = vk.w;
        }
        __syncthreads();

        #pragma unroll
        for (int k = 0; k < 32; k++) {
            float a[8], c[8];
            float4 a0 = *reinterpret_cast<const float4*>(&Qs[k][ty * 8]);
            float4 a1 = *reinterpret_cast<const float4*>(&Qs[k][ty * 8 + 4]);
            float4 c0 = *reinterpret_cast<const float4*>(&Ks[k][tx * 8]);
            float4 c1 = *reinterpret_cast<const float4*>(&Ks[k][tx * 8 + 4]);
            a[0]=a0.x; a[1]=a0.y; a[2]=a0.z; a[3]=a0.w;
            a[4]=a1.x; a[5]=a1.y; a[6]=a1.z; a[7]=a1.w;
            c[0]=c0.x; c[1]=c0.y; c[2]=c0.z; c[3]=c0.w;
            c[4]=c1.x; c[5]=c1.y; c[6]=c1.z; c[7]=c1.w;
            #pragma unroll
            for (int i = 0; i < 8; i++)
                #pragma unroll
                for (int j = 0; j < 8; j++)
                    acc[i][j] += a[i] * c[j];
        }
        __syncthreads();
    }

    // Epilogue: pad mask, causal(-1) mask, scale; vectorized store
    const size_t zbase = (size_t)z * S_ * S_;
    #pragma unroll
    for (int i = 0; i < 8; i++) {
        int m = m0 + ty * 8 + i;
        #pragma unroll
        for (int jj = 0; jj < 2; jj++) {
            float4 v;
            float* vp = reinterpret_cast<float*>(&v);
            #pragma unroll
            for (int l = 0; l < 4; l++) {
                int j  = jj * 4 + l;
                int n  = n0 + tx * 8 + j;
                float p = pads[tx * 8 + j];
                float t = acc[i][j] * p - (1.0f - p) * NEGC;
                if (m > n) t -= NEGC;
                vp[l] = t * 0.125f;
            }
            *reinterpret_cast<float4*>(
                &out[zbase + (size_t)m * S_ + n0 + tx * 8 + jj * 4]) = v;
        }
    }
}

// ---------------------------------------------------------------------------
extern "C" void kernel_launch(void* const* d_in, const int* in_sizes, int n_in,
                              void* d_out, int out_size) {
    const float* X    = (const float*)d_in[0];   // last_hidden_state [B,S,H]
    const float* W    = (const float*)d_in[1];   // dense_w [H, T*2*D]
    const float* bias = (const float*)d_in[2];   // dense_b [T*2*D]
    const float* mask = (const float*)d_in[3];   // attention_mask [B,S]
    float* out = (float*)d_out;                  // [B,T,S,S]

    rope_table_kernel<<<32, 256>>>();
    gemm1_rope_kernel<<<dim3(13, 128), 256>>>(X, W, bias);
    gemm2_mask_kernel<<<dim3(2, 2, 832), 256>>>(mask, out);
}

// round 3
// speedup vs baseline: 5.1484x; 5.1484x over previous
#include <cuda_runtime.h>
#include <cuda_bf16.h>
#include <math.h>
#include <stdint.h>

#define B_  64
#define S_  256
#define H_  768
#define T_  13
#define D_  64
#define NEGC 1000000000000.0f

#define M1 (B_*S_)      // 16384
#define N1 (T_*2*D_)    // 1664
#define K1 H_           // 768

typedef __nv_bfloat16  bf16;
typedef __nv_bfloat162 bf162;

// ------------------------- device scratch (no allocs) ----------------------
__device__ __align__(128) bf16 g_xb[(size_t)M1 * K1];           // X in bf16 [16384,768]
__device__ __align__(128) bf16 g_wt[(size_t)N1 * K1];           // W^T in bf16 [1664,768]
__device__ __align__(128) bf16 g_qb[(size_t)B_ * T_ * S_ * D_]; // q [b,h,s,d] bf16
__device__ __align__(128) bf16 g_kb[(size_t)B_ * T_ * S_ * D_]; // k [b,h,s,d] bf16
__device__ float g_cos[S_ * (D_/2)];
__device__ float g_sin[S_ * (D_/2)];

// ------------------------------ PTX helpers --------------------------------
__device__ __forceinline__ uint32_t smem_u32(const void* p) {
    return (uint32_t)__cvta_generic_to_shared(p);
}
__device__ __forceinline__ void cp16(uint32_t dst, const void* src) {
    asm volatile("cp.async.cg.shared.global [%0], [%1], 16;\n" :: "r"(dst), "l"(src));
}
__device__ __forceinline__ void cp_commit() {
    asm volatile("cp.async.commit_group;\n");
}
template<int N> __device__ __forceinline__ void cp_wait() {
    asm volatile("cp.async.wait_group %0;\n" :: "n"(N));
}
__device__ __forceinline__ void ldm_x4(uint32_t addr,
        uint32_t& r0, uint32_t& r1, uint32_t& r2, uint32_t& r3) {
    asm volatile("ldmatrix.sync.aligned.m8n8.x4.shared.b16 {%0,%1,%2,%3}, [%4];\n"
        : "=r"(r0), "=r"(r1), "=r"(r2), "=r"(r3) : "r"(addr));
}
__device__ __forceinline__ void mma_bf16(float* c,
        uint32_t a0, uint32_t a1, uint32_t a2, uint32_t a3,
        uint32_t b0, uint32_t b1) {
    asm volatile(
        "mma.sync.aligned.m16n8k16.row.col.f32.bf16.bf16.f32 "
        "{%0,%1,%2,%3}, {%4,%5,%6,%7}, {%8,%9}, {%0,%1,%2,%3};\n"
        : "+f"(c[0]), "+f"(c[1]), "+f"(c[2]), "+f"(c[3])
        : "r"(a0), "r"(a1), "r"(a2), "r"(a3), "r"(b0), "r"(b1));
}

// --------------------------- RoPE table (fp64) -----------------------------
__global__ void rope_table_kernel() {
    int idx = blockIdx.x * blockDim.x + threadIdx.x;
    if (idx >= S_ * (D_/2)) return;
    int s = idx >> 5;
    int i = idx & 31;
    double inv = pow(10000.0, -2.0 * (double)i / (double)D_);
    double ang = (double)s * inv;
    g_cos[idx] = (float)cos(ang);
    g_sin[idx] = (float)sin(ang);
}

// ----------------------- X fp32 -> bf16 (contiguous) -----------------------
__global__ void convert_x_kernel(const float* __restrict__ X) {
    int i = blockIdx.x * blockDim.x + threadIdx.x;  // float4 index, exact fit
    float4 v = reinterpret_cast<const float4*>(X)[i];
    bf162* o = reinterpret_cast<bf162*>(g_xb) + (size_t)i * 2;
    o[0] = __floats2bfloat162_rn(v.x, v.y);
    o[1] = __floats2bfloat162_rn(v.z, v.w);
}

// --------------- W [768,1664] fp32 -> W^T [1664,768] bf16 ------------------
__global__ void convert_w_kernel(const float* __restrict__ W) {
    __shared__ float t[32][33];
    int x0 = blockIdx.x * 32;   // N dim
    int y0 = blockIdx.y * 32;   // K dim
    int tx = threadIdx.x, ty = threadIdx.y;   // 32 x 8
    #pragma unroll
    for (int i = 0; i < 4; i++)
        t[ty + i*8][tx] = W[(size_t)(y0 + ty + i*8) * N1 + x0 + tx];
    __syncthreads();
    #pragma unroll
    for (int i = 0; i < 4; i++)
        g_wt[(size_t)(x0 + ty + i*8) * K1 + y0 + tx] =
            __float2bfloat16(t[tx][ty + i*8]);
}

// ---------------------------------------------------------------------------
// GEMM1: [16384x768] @ [768x1664] via bf16 mma.sync, fused bias+RoPE,
// scatter to g_qb / g_kb. CTA tile 128(M) x 128(N=one head), BK=64,
// double-buffered cp.async, XOR-swizzled SMEM, 8 warps (4x2), warp 32x64.
// ---------------------------------------------------------------------------
__global__ __launch_bounds__(256, 2) void gemm1_rope_bf16(
    const float* __restrict__ bias)
{
    extern __shared__ __align__(16) bf16 sm[];   // [A0|B0|A1|B1] each 8192 el

    const int tid  = threadIdx.x;
    const int lane = tid & 31;
    const int warp = tid >> 5;
    const int wm   = warp & 3;       // 0..3  (M)
    const int wn   = warp >> 2;      // 0..1  (N)
    const int h    = blockIdx.x;     // head 0..12
    const int m0   = blockIdx.y * 128;

    float acc[2][8][4];
    #pragma unroll
    for (int a = 0; a < 2; a++)
        #pragma unroll
        for (int b = 0; b < 8; b++)
            #pragma unroll
            for (int c = 0; c < 4; c++) acc[a][b][c] = 0.0f;

    const bf16* srcA = g_xb + (size_t)m0 * K1;
    const bf16* srcB = g_wt + (size_t)h * 128 * K1;

    // tile loader: 128 rows x 64 bf16 (8 chunks of 16B per row), swizzled
    auto load_tile = [&](int buf, int k0) {
        bf16* dA = sm + buf * 16384;
        bf16* dB = sm + buf * 16384 + 8192;
        #pragma unroll
        for (int t = 0; t < 4; t++) {
            int f = tid + t * 256;          // 0..1023
            int r = f >> 3;
            int c = f & 7;
            int sw = (c ^ (r & 7)) << 3;    // element offset of 16B chunk
            cp16(smem_u32(dA + r * 64 + sw), srcA + (size_t)r * K1 + k0 + c * 8);
            cp16(smem_u32(dB + r * 64 + sw), srcB + (size_t)r * K1 + k0 + c * 8);
        }
    };

    auto compute = [&](int buf) {
        const bf16* A  = sm + buf * 16384;
        const bf16* Bs = sm + buf * 16384 + 8192;
        #pragma unroll
        for (int ki = 0; ki < 4; ki++) {
            uint32_t a[2][4];
            #pragma unroll
            for (int mi = 0; mi < 2; mi++) {
                int row = wm * 32 + mi * 16 + (lane & 15);
                int kch = ki * 2 + (lane >> 4);
                uint32_t ad = smem_u32(A + row * 64 + ((kch ^ (row & 7)) << 3));
                ldm_x4(ad, a[mi][0], a[mi][1], a[mi][2], a[mi][3]);
            }
            #pragma unroll
            for (int njp = 0; njp < 4; njp++) {
                int mat  = lane >> 3;
                int rowb = wn * 64 + njp * 16 + ((mat >> 1) << 3) + (lane & 7);
                int kch  = ki * 2 + (mat & 1);
                uint32_t bd = smem_u32(Bs + rowb * 64 + ((kch ^ (rowb & 7)) << 3));
                uint32_t b0, b1, b2, b3;
                ldm_x4(bd, b0, b1, b2, b3);
                #pragma unroll
                for (int mi = 0; mi < 2; mi++) {
                    mma_bf16(acc[mi][njp*2],   a[mi][0], a[mi][1], a[mi][2], a[mi][3], b0, b1);
                    mma_bf16(acc[mi][njp*2+1], a[mi][0], a[mi][1], a[mi][2], a[mi][3], b2, b3);
                }
            }
        }
    };

    load_tile(0, 0);
    cp_commit();
    for (int it = 0; it < 12; it++) {
        if (it < 11) {
            load_tile((it + 1) & 1, (it + 1) * 64);
            cp_commit();
            cp_wait<1>();
        } else {
            cp_wait<0>();
        }
        __syncthreads();
        compute(it & 1);
        __syncthreads();
    }

    // Epilogue: bias + RoPE + bf16 scatter. c0,c1 = (row, n), (row, n+1);
    // c2,c3 = row+8. n pairs are adjacent -> RoPE pair inside one thread.
    const int hbase = h * 128;
    #pragma unroll
    for (int mi = 0; mi < 2; mi++) {
        #pragma unroll
        for (int nj = 0; nj < 8; nj++) {
            int ncl = wn * 64 + nj * 8 + ((lane & 3) << 1);   // 0..127, even
            int d   = ncl & 63;
            bf16* dst = (ncl < 64) ? g_qb : g_kb;
            float bx = bias[hbase + ncl];
            float by = bias[hbase + ncl + 1];
            int pi = d >> 1;
            #pragma unroll
            for (int hh = 0; hh < 2; hh++) {
                int row = m0 + wm * 32 + mi * 16 + (lane >> 2) + hh * 8;
                int bb  = row >> 8;
                int s   = row & 255;
                float x = acc[mi][nj][hh*2]     + bx;
                float y = acc[mi][nj][hh*2 + 1] + by;
                float cs = g_cos[s * 32 + pi];
                float sn = g_sin[s * 32 + pi];
                bf162 v;
                v.x = __float2bfloat16(x * cs - y * sn);
                v.y = __float2bfloat16(y * cs + x * sn);
                *reinterpret_cast<bf162*>(
                    &dst[((size_t)(bb * T_ + h) * S_ + s) * D_ + d]) = v;
            }
        }
    }
}

// ---------------------------------------------------------------------------
// GEMM2: per (b,h): logits = q @ k^T  (256x256x64), bf16 mma.sync,
// fused pad/causal masks + 0.125 scale. CTA = 128x128 tile, K=64 one shot.
// ---------------------------------------------------------------------------
__global__ __launch_bounds__(256, 2) void gemm2_bf16(
    const float* __restrict__ attn_mask, float* __restrict__ out)
{
    __shared__ __align__(16) bf16 Qs[8192];
    __shared__ __align__(16) bf16 Ks[8192];
    __shared__ float pads[128];

    const int tid  = threadIdx.x;
    const int lane = tid & 31;
    const int warp = tid >> 5;
    const int wm   = warp & 3;
    const int wn   = warp >> 2;
    const int z    = blockIdx.z;            // b*13 + h
    const int b    = z / T_;
    const int n0   = blockIdx.x * 128;
    const int m0   = blockIdx.y * 128;

    const bf16* qbase = g_qb + (size_t)z * S_ * D_;
    const bf16* kbase = g_kb + (size_t)z * S_ * D_;

    #pragma unroll
    for (int t = 0; t < 4; t++) {
        int f = tid + t * 256;
        int r = f >> 3;
        int c = f & 7;
        int sw = (c ^ (r & 7)) << 3;
        cp16(smem_u32(Qs + r * 64 + sw), qbase + (size_t)(m0 + r) * D_ + c * 8);
        cp16(smem_u32(Ks + r * 64 + sw), kbase + (size_t)(n0 + r) * D_ + c * 8);
    }
    if (tid < 128) pads[tid] = attn_mask[b * S_ + n0 + tid];
    cp_commit();
    cp_wait<0>();
    __syncthreads();

    float acc[2][8][4];
    #pragma unroll
    for (int a = 0; a < 2; a++)
        #pragma unroll
        for (int bb = 0; bb < 8; bb++)
            #pragma unroll
            for (int c = 0; c < 4; c++) acc[a][bb][c] = 0.0f;

    #pragma unroll
    for (int ki = 0; ki < 4; ki++) {
        uint32_t a[2][4];
        #pragma unroll
        for (int mi = 0; mi < 2; mi++) {
            int row = wm * 32 + mi * 16 + (lane & 15);
            int kch = ki * 2 + (lane >> 4);
            uint32_t ad = smem_u32(Qs + row * 64 + ((kch ^ (row & 7)) << 3));
            ldm_x4(ad, a[mi][0], a[mi][1], a[mi][2], a[mi][3]);
        }
        #pragma unroll
        for (int njp = 0; njp < 4; njp++) {
            int mat  = lane >> 3;
            int rowb = wn * 64 + njp * 16 + ((mat >> 1) << 3) + (lane & 7);
            int kch  = ki * 2 + (mat & 1);
            uint32_t bd = smem_u32(Ks + rowb * 64 + ((kch ^ (rowb & 7)) << 3));
            uint32_t b0, b1, b2, b3;
            ldm_x4(bd, b0, b1, b2, b3);
            #pragma unroll
            for (int mi = 0; mi < 2; mi++) {
                mma_bf16(acc[mi][njp*2],   a[mi][0], a[mi][1], a[mi][2], a[mi][3], b0, b1);
                mma_bf16(acc[mi][njp*2+1], a[mi][0], a[mi][1], a[mi][2], a[mi][3], b2, b3);
            }
        }
    }

    // Epilogue: pad mask, strict-lower causal, scale; float2 stores
    const size_t zbase = (size_t)z * S_ * S_;
    #pragma unroll
    for (int mi = 0; mi < 2; mi++) {
        #pragma unroll
        for (int nj = 0; nj < 8; nj++) {
            int ncl = wn * 64 + nj * 8 + ((lane & 3) << 1);
            int n   = n0 + ncl;
            float p0 = pads[ncl];
            float p1 = pads[ncl + 1];
            #pragma unroll
            for (int hh = 0; hh < 2; hh++) {
                int m = m0 + wm * 32 + mi * 16 + (lane >> 2) + hh * 8;
                float x = acc[mi][nj][hh*2];
                float y = acc[mi][nj][hh*2 + 1];
                float t0 = x * p0 - (1.0f - p0) * NEGC;
                float t1 = y * p1 - (1.0f - p1) * NEGC;
                if (m > n)     t0 -= NEGC;
                if (m > n + 1) t1 -= NEGC;
                float2 v = make_float2(t0 * 0.125f, t1 * 0.125f);
                *reinterpret_cast<float2*>(&out[zbase + (size_t)m * S_ + n]) = v;
            }
        }
    }
}

// ---------------------------------------------------------------------------
extern "C" void kernel_launch(void* const* d_in, const int* in_sizes, int n_in,
                              void* d_out, int out_size) {
    const float* X    = (const float*)d_in[0];   // [B,S,H]
    const float* W    = (const float*)d_in[1];   // [H, T*2*D]
    const float* bias = (const float*)d_in[2];   // [T*2*D]
    const float* mask = (const float*)d_in[3];   // [B,S]
    float* out = (float*)d_out;                  // [B,T,S,S]

    rope_table_kernel<<<32, 256>>>();
    convert_x_kernel<<<12288, 256>>>(X);
    convert_w_kernel<<<dim3(52, 24), dim3(32, 8)>>>(W);

    cudaFuncSetAttribute(gemm1_rope_bf16,
                         cudaFuncAttributeMaxDynamicSharedMemorySize, 65536);
    gemm1_rope_bf16<<<dim3(13, 128), 256, 65536>>>(bias);
    gemm2_bf16<<<dim3(2, 2, 832), 256>>>(mask, out);
}